// round 1
// baseline (speedup 1.0000x reference)
#include <cuda_runtime.h>
#include <math.h>

// ---------------------------------------------------------------------------
// Problem constants
//   N = 32768 tokens, C = 512, H = 8, D = 64
//   windows: 4x4x4 = 64 windows of 8x8x8 = 512 tokens
// ---------------------------------------------------------------------------

// Scratch (static device allocations — allowed; no cudaMalloc anywhere)
__device__ float g_q[64 * 8 * 512 * 64];   // [w][h][m][d]
__device__ float g_k[64 * 8 * 512 * 64];
__device__ float g_v[64 * 8 * 512 * 64];
__device__ float g_h[32768 * 512];         // [n][h*64+d]  (inverse-permuted)

// ---------------------------------------------------------------------------
// Packed f32x2 helpers (Blackwell double-rate fp32; only reachable via PTX)
// ---------------------------------------------------------------------------
__device__ __forceinline__ void fma2(unsigned long long& d,
                                     unsigned long long a,
                                     unsigned long long b) {
    asm("fma.rn.f32x2 %0, %1, %2, %3;" : "=l"(d) : "l"(a), "l"(b), "l"(d));
}
__device__ __forceinline__ unsigned long long pack2(float x, float y) {
    unsigned long long r;
    asm("mov.b64 %0, {%1, %2};" : "=l"(r) : "f"(x), "f"(y));
    return r;
}
__device__ __forceinline__ float2 unpack2(unsigned long long v) {
    float2 r;
    asm("mov.b64 {%0, %1}, %2;" : "=f"(r.x), "=f"(r.y) : "l"(v));
    return r;
}
__device__ __forceinline__ unsigned long long mul2(unsigned long long a,
                                                   unsigned long long b) {
    unsigned long long r;
    asm("mul.rn.f32x2 %0, %1, %2;" : "=l"(r) : "l"(a), "l"(b));
    return r;
}

// ---------------------------------------------------------------------------
// K1: QKV GEMM [32768,512] x [512,1536]  + bias + RMS-norm(q,k) + window scatter
// 64x64 tile per block, 256 threads, 4x4 micro-tile, f32x2 inner loop.
// Each 64-col tile is exactly one (section, head): sec = j0/512, head = (j0%512)/64
// ---------------------------------------------------------------------------
__global__ __launch_bounds__(256)
void qkv_norm_scatter(const float* __restrict__ x,
                      const float* __restrict__ wqkv,
                      const float* __restrict__ bqkv,
                      const int*   __restrict__ coords,
                      const float* __restrict__ gq,
                      const float* __restrict__ gk)
{
    __shared__ float As[64][20];   // [m][k], stride 20 floats (80B, f4-aligned, conflict-free)
    __shared__ float Bs[16][64];   // [k][j]

    const int tid = threadIdx.x;
    const int tx = tid & 15, ty = tid >> 4;
    const int m0 = blockIdx.y << 6;
    const int j0 = blockIdx.x << 6;

    unsigned long long acc[4][2];
#pragma unroll
    for (int i = 0; i < 4; i++) { acc[i][0] = 0ull; acc[i][1] = 0ull; }

    const int arow = tid >> 2, acol = (tid & 3) << 2;   // A: 64 rows x 16 k
    const int brow = tid >> 4, bcol = (tid & 15) << 2;  // B: 16 rows x 64 j
    const float* aptr = x + (size_t)(m0 + arow) * 512 + acol;
    const float* bptr = wqkv + (size_t)brow * 1536 + j0 + bcol;

    for (int k0 = 0; k0 < 512; k0 += 16) {
        float4 av = *(const float4*)(aptr + k0);
        float4 bv = *(const float4*)(bptr + (size_t)k0 * 1536);
        *(float4*)&As[arow][acol] = av;
        *(float4*)&Bs[brow][bcol] = bv;
        __syncthreads();
#pragma unroll
        for (int kk = 0; kk < 16; kk++) {
            unsigned long long b0 = *(const unsigned long long*)&Bs[kk][tx << 2];
            unsigned long long b1 = *(const unsigned long long*)(&Bs[kk][tx << 2] + 2);
#pragma unroll
            for (int i = 0; i < 4; i++) {
                float a = As[(ty << 2) + i][kk];
                unsigned long long pa = pack2(a, a);
                fma2(acc[i][0], pa, b0);
                fma2(acc[i][1], pa, b1);
            }
        }
        __syncthreads();
    }

    const int sec  = j0 >> 9;          // 0=q, 1=k, 2=v
    const int head = (j0 >> 6) & 7;

    float bias[4], gam[4];
#pragma unroll
    for (int jj = 0; jj < 4; jj++) {
        bias[jj] = bqkv[j0 + (tx << 2) + jj];
        gam[jj] = 1.0f;
    }
    if (sec == 0) {
#pragma unroll
        for (int jj = 0; jj < 4; jj++) gam[jj] = gq[head * 64 + (tx << 2) + jj];
    } else if (sec == 1) {
#pragma unroll
        for (int jj = 0; jj < 4; jj++) gam[jj] = gk[head * 64 + (tx << 2) + jj];
    }

    float out[4][4];
#pragma unroll
    for (int i = 0; i < 4; i++) {
        float2 v0 = unpack2(acc[i][0]);
        float2 v1 = unpack2(acc[i][1]);
        out[i][0] = v0.x + bias[0];
        out[i][1] = v0.y + bias[1];
        out[i][2] = v1.x + bias[2];
        out[i][3] = v1.y + bias[3];
    }

    if (sec < 2) {
        // RMS norm over the 64-dim head: reduce sumsq across the 16 tx lanes
#pragma unroll
        for (int i = 0; i < 4; i++) {
            float ss = out[i][0] * out[i][0] + out[i][1] * out[i][1]
                     + out[i][2] * out[i][2] + out[i][3] * out[i][3];
            ss += __shfl_xor_sync(0xffffffffu, ss, 1);
            ss += __shfl_xor_sync(0xffffffffu, ss, 2);
            ss += __shfl_xor_sync(0xffffffffu, ss, 4);
            ss += __shfl_xor_sync(0xffffffffu, ss, 8);
            float inv = 8.0f / fmaxf(sqrtf(ss), 1e-12f);   // sqrt(D)=8
#pragma unroll
            for (int jj = 0; jj < 4; jj++) out[i][jj] *= inv * gam[jj];
        }
    }

    float* dst = (sec == 0) ? g_q : ((sec == 1) ? g_k : g_v);
#pragma unroll
    for (int i = 0; i < 4; i++) {
        int n = m0 + (ty << 2) + i;
        int cx = coords[4 * n + 1], cy = coords[4 * n + 2], cz = coords[4 * n + 3];
        int w = ((cx >> 3) << 4) + ((cy >> 3) << 2) + (cz >> 3);
        int m = ((cz & 7) << 6) + ((cy & 7) << 3) + (cx & 7);
        float4 o4 = make_float4(out[i][0], out[i][1], out[i][2], out[i][3]);
        *(float4*)&dst[((size_t)((w << 3) + head) * 512 + m) * 64 + (tx << 2)] = o4;
    }
}

// ---------------------------------------------------------------------------
// K2: window attention. One block per (w, h, 64-query tile).
// Flash-style online softmax over 8 key chunks of 64 keys. f32x2 GEMMs.
// ---------------------------------------------------------------------------
#define ATTN_SMEM_FLOATS (4096 + 64 * 65 + 4096 + 4096)
#define ATTN_SMEM_BYTES  (ATTN_SMEM_FLOATS * 4)

__global__ __launch_bounds__(256)
void window_attn()
{
    extern __shared__ float sm[];
    float* Qs = sm;              // [64][64]
    float* Ks = Qs + 4096;       // [64][65]  (pad to avoid broadside conflicts)
    float* Vs = Ks + 64 * 65;    // [64][64]
    float* Ps = Vs + 4096;       // [64][64]

    const int tid = threadIdx.x;
    const int tx = tid & 15, ty = tid >> 4;
    const int qt = blockIdx.x & 7;
    const int wh = blockIdx.x >> 3;   // w*8 + h

    const float* qbase = g_q + ((size_t)wh * 512 + (size_t)qt * 64) * 64;
    const float* kbase = g_k + (size_t)wh * 512 * 64;
    const float* vbase = g_v + (size_t)wh * 512 * 64;

#pragma unroll
    for (int p = 0; p < 4; p++) {
        int idx = p * 1024 + tid * 4;
        *(float4*)&Qs[idx] = *(const float4*)&qbase[idx];
    }

    float mrow[4], lrow[4];
    unsigned long long accO[4][2];
#pragma unroll
    for (int i = 0; i < 4; i++) {
        mrow[i] = -1e30f; lrow[i] = 0.f;
        accO[i][0] = 0ull; accO[i][1] = 0ull;
    }

    for (int c = 0; c < 8; c++) {
        __syncthreads();   // prior chunk's Ps/Vs reads done; safe to overwrite K/V
#pragma unroll
        for (int p = 0; p < 4; p++) {
            int idx = p * 1024 + tid * 4;
            int n = idx >> 6, d = idx & 63;
            float4 kv = *(const float4*)&kbase[c * 4096 + idx];
            Ks[n * 65 + d]     = kv.x;
            Ks[n * 65 + d + 1] = kv.y;
            Ks[n * 65 + d + 2] = kv.z;
            Ks[n * 65 + d + 3] = kv.w;
            *(float4*)&Vs[idx] = *(const float4*)&vbase[c * 4096 + idx];
        }
        __syncthreads();

        // S tile = Q (64x64) @ K^T (64x64)
        unsigned long long s2[4][2];
#pragma unroll
        for (int i = 0; i < 4; i++) { s2[i][0] = 0ull; s2[i][1] = 0ull; }
#pragma unroll 16
        for (int d = 0; d < 64; d++) {
            float k0 = Ks[((tx << 2) + 0) * 65 + d];
            float k1 = Ks[((tx << 2) + 1) * 65 + d];
            float k2 = Ks[((tx << 2) + 2) * 65 + d];
            float k3 = Ks[((tx << 2) + 3) * 65 + d];
            unsigned long long b0 = pack2(k0, k1);
            unsigned long long b1 = pack2(k2, k3);
#pragma unroll
            for (int i = 0; i < 4; i++) {
                float a = Qs[((ty << 2) + i) * 64 + d];
                unsigned long long pa = pack2(a, a);
                fma2(s2[i][0], pa, b0);
                fma2(s2[i][1], pa, b1);
            }
        }

        // online softmax update (rows reduced across 16 tx lanes)
#pragma unroll
        for (int i = 0; i < 4; i++) {
            float2 v0 = unpack2(s2[i][0]);
            float2 v1 = unpack2(s2[i][1]);
            float s0 = v0.x * 0.125f;   // 1/sqrt(64)
            float s1 = v0.y * 0.125f;
            float sc2 = v1.x * 0.125f;
            float s3 = v1.y * 0.125f;
            float cm = fmaxf(fmaxf(s0, s1), fmaxf(sc2, s3));
            cm = fmaxf(cm, __shfl_xor_sync(0xffffffffu, cm, 1));
            cm = fmaxf(cm, __shfl_xor_sync(0xffffffffu, cm, 2));
            cm = fmaxf(cm, __shfl_xor_sync(0xffffffffu, cm, 4));
            cm = fmaxf(cm, __shfl_xor_sync(0xffffffffu, cm, 8));
            float mnew = fmaxf(mrow[i], cm);
            float corr = __expf(mrow[i] - mnew);
            mrow[i] = mnew;
            float p0 = __expf(s0 - mnew);
            float p1 = __expf(s1 - mnew);
            float p2 = __expf(sc2 - mnew);
            float p3 = __expf(s3 - mnew);
            float rs = p0 + p1 + p2 + p3;
            rs += __shfl_xor_sync(0xffffffffu, rs, 1);
            rs += __shfl_xor_sync(0xffffffffu, rs, 2);
            rs += __shfl_xor_sync(0xffffffffu, rs, 4);
            rs += __shfl_xor_sync(0xffffffffu, rs, 8);
            lrow[i] = lrow[i] * corr + rs;
            unsigned long long pc = pack2(corr, corr);
            accO[i][0] = mul2(accO[i][0], pc);
            accO[i][1] = mul2(accO[i][1], pc);
            *(float4*)&Ps[((ty << 2) + i) * 64 + (tx << 2)] =
                make_float4(p0, p1, p2, p3);
        }
        __syncthreads();

        // O += P (64x64) @ V (64x64)
#pragma unroll 16
        for (int n = 0; n < 64; n++) {
            unsigned long long b0 = *(const unsigned long long*)&Vs[n * 64 + (tx << 2)];
            unsigned long long b1 = *(const unsigned long long*)&Vs[n * 64 + (tx << 2) + 2];
#pragma unroll
            for (int i = 0; i < 4; i++) {
                float a = Ps[((ty << 2) + i) * 64 + n];
                unsigned long long pa = pack2(a, a);
                fma2(accO[i][0], pa, b0);
                fma2(accO[i][1], pa, b1);
            }
        }
    }

    // epilogue: divide by l, scatter through inverse window permutation
    const int w = wh >> 3, h = wh & 7;
    const int wx = w >> 4, wy = (w >> 2) & 3, wz = w & 3;
#pragma unroll
    for (int i = 0; i < 4; i++) {
        int m = (qt << 6) + (ty << 2) + i;
        int mz = m >> 6, my = (m >> 3) & 7, mx = m & 7;
        int n = (wz * 8 + mz) * 1024 + (wy * 8 + my) * 32 + (wx * 8 + mx);
        float invl = 1.0f / lrow[i];
        float2 v0 = unpack2(accO[i][0]);
        float2 v1 = unpack2(accO[i][1]);
        *(float4*)&g_h[(size_t)n * 512 + h * 64 + (tx << 2)] =
            make_float4(v0.x * invl, v0.y * invl, v1.x * invl, v1.y * invl);
    }
}

// ---------------------------------------------------------------------------
// K3: output projection  [32768,512] x [512,512] + bias -> d_out
// ---------------------------------------------------------------------------
__global__ __launch_bounds__(256)
void out_proj(const float* __restrict__ wout,
              const float* __restrict__ bout,
              float* __restrict__ outp)
{
    __shared__ float As[64][20];
    __shared__ float Bs[16][64];

    const int tid = threadIdx.x;
    const int tx = tid & 15, ty = tid >> 4;
    const int m0 = blockIdx.y << 6;
    const int j0 = blockIdx.x << 6;

    unsigned long long acc[4][2];
#pragma unroll
    for (int i = 0; i < 4; i++) { acc[i][0] = 0ull; acc[i][1] = 0ull; }

    const int arow = tid >> 2, acol = (tid & 3) << 2;
    const int brow = tid >> 4, bcol = (tid & 15) << 2;
    const float* aptr = g_h + (size_t)(m0 + arow) * 512 + acol;
    const float* bptr = wout + (size_t)brow * 512 + j0 + bcol;

    for (int k0 = 0; k0 < 512; k0 += 16) {
        float4 av = *(const float4*)(aptr + k0);
        float4 bv = *(const float4*)(bptr + (size_t)k0 * 512);
        *(float4*)&As[arow][acol] = av;
        *(float4*)&Bs[brow][bcol] = bv;
        __syncthreads();
#pragma unroll
        for (int kk = 0; kk < 16; kk++) {
            unsigned long long b0 = *(const unsigned long long*)&Bs[kk][tx << 2];
            unsigned long long b1 = *(const unsigned long long*)(&Bs[kk][tx << 2] + 2);
#pragma unroll
            for (int i = 0; i < 4; i++) {
                float a = As[(ty << 2) + i][kk];
                unsigned long long pa = pack2(a, a);
                fma2(acc[i][0], pa, b0);
                fma2(acc[i][1], pa, b1);
            }
        }
        __syncthreads();
    }

    float bias[4];
#pragma unroll
    for (int jj = 0; jj < 4; jj++) bias[jj] = bout[j0 + (tx << 2) + jj];

#pragma unroll
    for (int i = 0; i < 4; i++) {
        float2 v0 = unpack2(acc[i][0]);
        float2 v1 = unpack2(acc[i][1]);
        *(float4*)&outp[(size_t)(m0 + (ty << 2) + i) * 512 + j0 + (tx << 2)] =
            make_float4(v0.x + bias[0], v0.y + bias[1], v1.x + bias[2], v1.y + bias[3]);
    }
}

// ---------------------------------------------------------------------------
// kernel_launch
// inputs: x_feats, coords, w_qkv, b_qkv, gamma_q, gamma_k, w_out, b_out
// ---------------------------------------------------------------------------
extern "C" void kernel_launch(void* const* d_in, const int* in_sizes, int n_in,
                              void* d_out, int out_size)
{
    (void)in_sizes; (void)n_in; (void)out_size;
    const float* x      = (const float*)d_in[0];
    const int*   coords = (const int*)  d_in[1];
    const float* wqkv   = (const float*)d_in[2];
    const float* bqkv   = (const float*)d_in[3];
    const float* gq     = (const float*)d_in[4];
    const float* gk     = (const float*)d_in[5];
    const float* wout   = (const float*)d_in[6];
    const float* bout   = (const float*)d_in[7];
    float* outp = (float*)d_out;

    cudaFuncSetAttribute(window_attn,
                         cudaFuncAttributeMaxDynamicSharedMemorySize,
                         ATTN_SMEM_BYTES);

    qkv_norm_scatter<<<dim3(24, 512), 256>>>(x, wqkv, bqkv, coords, gq, gk);
    window_attn<<<4096, 256, ATTN_SMEM_BYTES>>>();
    out_proj<<<dim3(8, 512), 256>>>(wout, bout, outp);
}

// round 4
// speedup vs baseline: 1.8636x; 1.8636x over previous
#include <cuda_runtime.h>
#include <math.h>
#include <stdint.h>

// ---------------------------------------------------------------------------
// Problem constants: N=32768 tokens, C=512, H=8, D=64; 64 windows x 512 tokens
// ---------------------------------------------------------------------------

// Scratch (static device arrays; no allocations anywhere)
__device__ float g_q[64 * 8 * 512 * 64];   // [w][h][m][d]
__device__ float g_k[64 * 8 * 512 * 64];
__device__ float g_v[64 * 8 * 512 * 64];
__device__ float g_h[32768 * 512];         // [n][h*64+d] (inverse-permuted)
__device__ float g_wqkvT[1536 * 512];      // wqkv transposed: [j][k]
__device__ float g_woutT[512 * 512];       // wout  transposed: [j][k]

// ---------------------------------------------------------------------------
// Helpers
// ---------------------------------------------------------------------------
__device__ __forceinline__ uint32_t cvt_tf32(float f) {
    uint32_t u; asm("cvt.rna.tf32.f32 %0, %1;" : "=r"(u) : "f"(f)); return u;
}

__device__ __forceinline__ void mma_tf32(float c[4], uint32_t a0, uint32_t a1,
                                         uint32_t a2, uint32_t a3,
                                         uint32_t b0, uint32_t b1) {
    asm volatile(
        "mma.sync.aligned.m16n8k8.row.col.f32.tf32.tf32.f32 "
        "{%0,%1,%2,%3}, {%4,%5,%6,%7}, {%8,%9}, {%0,%1,%2,%3};"
        : "+f"(c[0]), "+f"(c[1]), "+f"(c[2]), "+f"(c[3])
        : "r"(a0), "r"(a1), "r"(a2), "r"(a3), "r"(b0), "r"(b1));
}

// Packed f32x2 helpers (fp32 attention kernel)
__device__ __forceinline__ void fma2(unsigned long long& d,
                                     unsigned long long a, unsigned long long b) {
    asm("fma.rn.f32x2 %0, %1, %2, %3;" : "=l"(d) : "l"(a), "l"(b), "l"(d));
}
__device__ __forceinline__ unsigned long long pack2(float x, float y) {
    unsigned long long r;
    asm("mov.b64 %0, {%1, %2};" : "=l"(r) : "f"(x), "f"(y));
    return r;
}
__device__ __forceinline__ float2 unpack2(unsigned long long v) {
    float2 r;
    asm("mov.b64 {%0, %1}, %2;" : "=f"(r.x), "=f"(r.y) : "l"(v));
    return r;
}
__device__ __forceinline__ unsigned long long mul2(unsigned long long a,
                                                   unsigned long long b) {
    unsigned long long r;
    asm("mul.rn.f32x2 %0, %1, %2;" : "=l"(r) : "l"(a), "l"(b));
    return r;
}

// ---------------------------------------------------------------------------
// K0: 2D transpose dst[C][R] = src[R][C]
// ---------------------------------------------------------------------------
__global__ void transpose_k(const float* __restrict__ src,
                            float* __restrict__ dst, int R, int C)
{
    __shared__ float t[32][33];
    int bx = blockIdx.x << 5, by = blockIdx.y << 5;
    int x = threadIdx.x, y = threadIdx.y;   // 32 x 8
#pragma unroll
    for (int i = 0; i < 32; i += 8)
        t[y + i][x] = src[(size_t)(by + y + i) * C + bx + x];
    __syncthreads();
#pragma unroll
    for (int i = 0; i < 32; i += 8)
        dst[(size_t)(bx + y + i) * R + by + x] = t[x][y + i];
}

// ---------------------------------------------------------------------------
// tf32 mma.sync GEMM: C[128,128] tile of A[?,512] * BT[?,512]^T, K=512.
// Fragment-layout smem staging (see R3 derivation); XOR-swizzled by k-tile so
// consumers fetch whole fragments with single LDS.128s.
// Warp layout: 8 warps, warp tile 64x32 (wm = wid&1, wn = wid>>1).
// mode 0: QKV epilogue (bias + RMS-norm(q,k) + window scatter)
// mode 1: out-proj epilogue (bias + store)
// ---------------------------------------------------------------------------
__global__ __launch_bounds__(256, 2)
void gemm_mma(const float* __restrict__ A, const float* __restrict__ BT,
              const float* __restrict__ bias, const int* __restrict__ coords,
              const float* __restrict__ gq, const float* __restrict__ gk,
              float* __restrict__ outp, int mode)
{
    __shared__ float sA[4096];
    __shared__ float sB[4096];
    __shared__ float sBias[128];
    __shared__ float sGam[128];
    __shared__ float sRed[128][4];

    const int tid = threadIdx.x;
    const int lane = tid & 31, wid = tid >> 5;
    const int wm = wid & 1, wn = wid >> 1;
    const int gid = lane >> 2, tig = lane & 3;
    const int m0 = blockIdx.y << 7;
    const int j0 = blockIdx.x << 7;
    const int sec = j0 >> 9;

    if (tid < 128) {
        sBias[tid] = bias[j0 + tid];
        float g = 1.0f;
        if (mode == 0) {
            if (sec == 0) g = gq[(j0 & 511) + tid];
            else if (sec == 1) g = gk[(j0 & 511) + tid];
        }
        sGam[tid] = g;
    }

    float c[4][4][4];
#pragma unroll
    for (int mi = 0; mi < 4; mi++)
#pragma unroll
        for (int ni = 0; ni < 4; ni++)
#pragma unroll
            for (int q = 0; q < 4; q++) c[mi][ni][q] = 0.f;

    for (int s = 0; s < 16; s++) {
        const int kb = s << 5;
        if (s) __syncthreads();
        // ---- produce A ----
#pragma unroll
        for (int p = 0; p < 4; p++) {
            int idx = (p << 8) + tid;             // 0..1023
            int r = idx >> 3, cq = idx & 7;
            int tk = cq >> 1;
            float4 v = *(const float4*)&A[(size_t)(m0 + r) * 512 + kb + (cq << 2)];
            int base = ((((r >> 4) << 2) + tk) << 7) + ((r & 7) << 4)
                     + ((r >> 3) & 1) + ((cq & 1) << 1);
            sA[base + ((0 ^ tk) << 2)] = __uint_as_float(cvt_tf32(v.x));
            sA[base + ((1 ^ tk) << 2)] = __uint_as_float(cvt_tf32(v.y));
            sA[base + ((2 ^ tk) << 2)] = __uint_as_float(cvt_tf32(v.z));
            sA[base + ((3 ^ tk) << 2)] = __uint_as_float(cvt_tf32(v.w));
        }
        // ---- produce B ----
#pragma unroll
        for (int p = 0; p < 4; p++) {
            int idx = (p << 8) + tid;
            int n = idx >> 3, kq = idx & 7;
            int tk = kq >> 1;
            float4 v = *(const float4*)&BT[(size_t)(j0 + n) * 512 + kb + (kq << 2)];
            int base = ((((n >> 4) << 2) + tk) << 7) + ((n & 7) << 4)
                     + ((kq & 1)) + (((n >> 3) & 1) << 1);
            sB[base + ((0 ^ tk) << 2)] = __uint_as_float(cvt_tf32(v.x));
            sB[base + ((1 ^ tk) << 2)] = __uint_as_float(cvt_tf32(v.y));
            sB[base + ((2 ^ tk) << 2)] = __uint_as_float(cvt_tf32(v.z));
            sB[base + ((3 ^ tk) << 2)] = __uint_as_float(cvt_tf32(v.w));
        }
        __syncthreads();
        // ---- consume: 4 k8 steps ----
#pragma unroll
        for (int tk = 0; tk < 4; tk++) {
            const int lx = ((lane ^ tk) << 2);
            uint4 a[4];
#pragma unroll
            for (int mi = 0; mi < 4; mi++)
                a[mi] = *(const uint4*)&sA[(((((wm << 2) + mi) << 2) + tk) << 7) + lx];
            uint4 b[2];
#pragma unroll
            for (int pi = 0; pi < 2; pi++)
                b[pi] = *(const uint4*)&sB[(((((wn << 1) + pi) << 2) + tk) << 7) + lx];
#pragma unroll
            for (int mi = 0; mi < 4; mi++)
#pragma unroll
                for (int pi = 0; pi < 2; pi++) {
                    mma_tf32(c[mi][pi * 2],     a[mi].x, a[mi].y, a[mi].z, a[mi].w,
                             b[pi].x, b[pi].y);
                    mma_tf32(c[mi][pi * 2 + 1], a[mi].x, a[mi].y, a[mi].z, a[mi].w,
                             b[pi].z, b[pi].w);
                }
        }
    }

    // ------------------------------ epilogue -------------------------------
    if (mode == 1) {
#pragma unroll
        for (int mi = 0; mi < 4; mi++)
#pragma unroll
            for (int ni = 0; ni < 4; ni++) {
                int col = (wn << 5) + (ni << 3) + (tig << 1);
                int rlo = m0 + (wm << 6) + (mi << 4) + gid;
                float2 v0 = make_float2(c[mi][ni][0] + sBias[col],
                                        c[mi][ni][1] + sBias[col + 1]);
                float2 v1 = make_float2(c[mi][ni][2] + sBias[col],
                                        c[mi][ni][3] + sBias[col + 1]);
                *(float2*)&outp[(size_t)rlo * 512 + j0 + col] = v0;
                *(float2*)&outp[(size_t)(rlo + 8) * 512 + j0 + col] = v1;
            }
        return;
    }

    // mode 0: bias
#pragma unroll
    for (int mi = 0; mi < 4; mi++)
#pragma unroll
        for (int ni = 0; ni < 4; ni++) {
            int col = (wn << 5) + (ni << 3) + (tig << 1);
            c[mi][ni][0] += sBias[col];
            c[mi][ni][1] += sBias[col + 1];
            c[mi][ni][2] += sBias[col];
            c[mi][ni][3] += sBias[col + 1];
        }

    if (sec < 2) {
        // RMS norm: row sumsq over 64-col head.  Warp covers 32 cols; reduce
        // over tig (shfl), then pair warps (wn, wn^1) through smem.
#pragma unroll
        for (int mi = 0; mi < 4; mi++)
#pragma unroll
            for (int h = 0; h < 2; h++) {
                float ss = 0.f;
#pragma unroll
                for (int ni = 0; ni < 4; ni++) {
                    float x0 = c[mi][ni][2 * h], x1 = c[mi][ni][2 * h + 1];
                    ss += x0 * x0 + x1 * x1;
                }
                ss += __shfl_xor_sync(0xffffffffu, ss, 1);
                ss += __shfl_xor_sync(0xffffffffu, ss, 2);
                if (tig == 0)
                    sRed[(wm << 6) + (mi << 4) + gid + (h << 3)][wn] = ss;
            }
        __syncthreads();
#pragma unroll
        for (int mi = 0; mi < 4; mi++)
#pragma unroll
            for (int h = 0; h < 2; h++) {
                int rl = (wm << 6) + (mi << 4) + gid + (h << 3);
                float tot = sRed[rl][wn] + sRed[rl][wn ^ 1];
                float inv = 8.0f / fmaxf(sqrtf(tot), 1e-12f);
#pragma unroll
                for (int ni = 0; ni < 4; ni++) {
                    int col = (wn << 5) + (ni << 3) + (tig << 1);
                    c[mi][ni][2 * h]     *= inv * sGam[col];
                    c[mi][ni][2 * h + 1] *= inv * sGam[col + 1];
                }
            }
    }

    // window scatter
    float* dst = (sec == 0) ? g_q : ((sec == 1) ? g_k : g_v);
    const int head = ((j0 & 511) >> 6) + (wn >> 1);
    const int dbase = ((wn & 1) << 5) + (tig << 1);
#pragma unroll
    for (int mi = 0; mi < 4; mi++)
#pragma unroll
        for (int h = 0; h < 2; h++) {
            int token = m0 + (wm << 6) + (mi << 4) + gid + (h << 3);
            int cx = coords[4 * token + 1];
            int cy = coords[4 * token + 2];
            int cz = coords[4 * token + 3];
            int w = ((cx >> 3) << 4) + ((cy >> 3) << 2) + (cz >> 3);
            int m = ((cz & 7) << 6) + ((cy & 7) << 3) + (cx & 7);
            size_t bb = ((size_t)((w << 3) + head) * 512 + m) * 64 + dbase;
#pragma unroll
            for (int ni = 0; ni < 4; ni++)
                *(float2*)&dst[bb + (ni << 3)] =
                    make_float2(c[mi][ni][2 * h], c[mi][ni][2 * h + 1]);
        }
}

// ---------------------------------------------------------------------------
// K2: window attention (unchanged; fp32 + f32x2)
// ---------------------------------------------------------------------------
#define ATTN_SMEM_FLOATS (4096 + 64 * 65 + 4096 + 4096)
#define ATTN_SMEM_BYTES  (ATTN_SMEM_FLOATS * 4)

__global__ __launch_bounds__(256)
void window_attn()
{
    extern __shared__ float sm[];
    float* Qs = sm;              // [64][64]
    float* Ks = Qs + 4096;       // [64][65]
    float* Vs = Ks + 64 * 65;    // [64][64]
    float* Ps = Vs + 4096;       // [64][64]

    const int tid = threadIdx.x;
    const int tx = tid & 15, ty = tid >> 4;
    const int qt = blockIdx.x & 7;
    const int wh = blockIdx.x >> 3;   // w*8 + h

    const float* qbase = g_q + ((size_t)wh * 512 + (size_t)qt * 64) * 64;
    const float* kbase = g_k + (size_t)wh * 512 * 64;
    const float* vbase = g_v + (size_t)wh * 512 * 64;

#pragma unroll
    for (int p = 0; p < 4; p++) {
        int idx = p * 1024 + tid * 4;
        *(float4*)&Qs[idx] = *(const float4*)&qbase[idx];
    }

    float mrow[4], lrow[4];
    unsigned long long accO[4][2];
#pragma unroll
    for (int i = 0; i < 4; i++) {
        mrow[i] = -1e30f; lrow[i] = 0.f;
        accO[i][0] = 0ull; accO[i][1] = 0ull;
    }

    for (int c = 0; c < 8; c++) {
        __syncthreads();
#pragma unroll
        for (int p = 0; p < 4; p++) {
            int idx = p * 1024 + tid * 4;
            int n = idx >> 6, d = idx & 63;
            float4 kv = *(const float4*)&kbase[c * 4096 + idx];
            Ks[n * 65 + d]     = kv.x;
            Ks[n * 65 + d + 1] = kv.y;
            Ks[n * 65 + d + 2] = kv.z;
            Ks[n * 65 + d + 3] = kv.w;
            *(float4*)&Vs[idx] = *(const float4*)&vbase[c * 4096 + idx];
        }
        __syncthreads();

        unsigned long long s2[4][2];
#pragma unroll
        for (int i = 0; i < 4; i++) { s2[i][0] = 0ull; s2[i][1] = 0ull; }
#pragma unroll 16
        for (int d = 0; d < 64; d++) {
            float k0 = Ks[((tx << 2) + 0) * 65 + d];
            float k1 = Ks[((tx << 2) + 1) * 65 + d];
            float k2 = Ks[((tx << 2) + 2) * 65 + d];
            float k3 = Ks[((tx << 2) + 3) * 65 + d];
            unsigned long long b0 = pack2(k0, k1);
            unsigned long long b1 = pack2(k2, k3);
#pragma unroll
            for (int i = 0; i < 4; i++) {
                float a = Qs[((ty << 2) + i) * 64 + d];
                unsigned long long pa = pack2(a, a);
                fma2(s2[i][0], pa, b0);
                fma2(s2[i][1], pa, b1);
            }
        }

#pragma unroll
        for (int i = 0; i < 4; i++) {
            float2 v0 = unpack2(s2[i][0]);
            float2 v1 = unpack2(s2[i][1]);
            float s0 = v0.x * 0.125f;
            float s1 = v0.y * 0.125f;
            float sc2 = v1.x * 0.125f;
            float s3 = v1.y * 0.125f;
            float cm = fmaxf(fmaxf(s0, s1), fmaxf(sc2, s3));
            cm = fmaxf(cm, __shfl_xor_sync(0xffffffffu, cm, 1));
            cm = fmaxf(cm, __shfl_xor_sync(0xffffffffu, cm, 2));
            cm = fmaxf(cm, __shfl_xor_sync(0xffffffffu, cm, 4));
            cm = fmaxf(cm, __shfl_xor_sync(0xffffffffu, cm, 8));
            float mnew = fmaxf(mrow[i], cm);
            float corr = __expf(mrow[i] - mnew);
            mrow[i] = mnew;
            float p0 = __expf(s0 - mnew);
            float p1 = __expf(s1 - mnew);
            float p2 = __expf(sc2 - mnew);
            float p3 = __expf(s3 - mnew);
            float rs = p0 + p1 + p2 + p3;
            rs += __shfl_xor_sync(0xffffffffu, rs, 1);
            rs += __shfl_xor_sync(0xffffffffu, rs, 2);
            rs += __shfl_xor_sync(0xffffffffu, rs, 4);
            rs += __shfl_xor_sync(0xffffffffu, rs, 8);
            lrow[i] = lrow[i] * corr + rs;
            unsigned long long pc = pack2(corr, corr);
            accO[i][0] = mul2(accO[i][0], pc);
            accO[i][1] = mul2(accO[i][1], pc);
            *(float4*)&Ps[((ty << 2) + i) * 64 + (tx << 2)] =
                make_float4(p0, p1, p2, p3);
        }
        __syncthreads();

#pragma unroll 16
        for (int n = 0; n < 64; n++) {
            unsigned long long b0 = *(const unsigned long long*)&Vs[n * 64 + (tx << 2)];
            unsigned long long b1 = *(const unsigned long long*)&Vs[n * 64 + (tx << 2) + 2];
#pragma unroll
            for (int i = 0; i < 4; i++) {
                float a = Ps[((ty << 2) + i) * 64 + n];
                unsigned long long pa = pack2(a, a);
                fma2(accO[i][0], pa, b0);
                fma2(accO[i][1], pa, b1);
            }
        }
    }

    const int w = wh >> 3, h = wh & 7;
    const int wx = w >> 4, wy = (w >> 2) & 3, wz = w & 3;
#pragma unroll
    for (int i = 0; i < 4; i++) {
        int m = (qt << 6) + (ty << 2) + i;
        int mz = m >> 6, my = (m >> 3) & 7, mx = m & 7;
        int n = (wz * 8 + mz) * 1024 + (wy * 8 + my) * 32 + (wx * 8 + mx);
        float invl = 1.0f / lrow[i];
        float2 v0 = unpack2(accO[i][0]);
        float2 v1 = unpack2(accO[i][1]);
        *(float4*)&g_h[(size_t)n * 512 + h * 64 + (tx << 2)] =
            make_float4(v0.x * invl, v0.y * invl, v1.x * invl, v1.y * invl);
    }
}

// ---------------------------------------------------------------------------
// kernel_launch
// inputs: x_feats, coords, w_qkv, b_qkv, gamma_q, gamma_k, w_out, b_out
// ---------------------------------------------------------------------------
extern "C" void kernel_launch(void* const* d_in, const int* in_sizes, int n_in,
                              void* d_out, int out_size)
{
    (void)in_sizes; (void)n_in; (void)out_size;
    const float* x      = (const float*)d_in[0];
    const int*   coords = (const int*)  d_in[1];
    const float* wqkv   = (const float*)d_in[2];
    const float* bqkv   = (const float*)d_in[3];
    const float* gq     = (const float*)d_in[4];
    const float* gk     = (const float*)d_in[5];
    const float* wout   = (const float*)d_in[6];
    const float* bout   = (const float*)d_in[7];
    float* outp = (float*)d_out;

    cudaFuncSetAttribute(window_attn,
                         cudaFuncAttributeMaxDynamicSharedMemorySize,
                         ATTN_SMEM_BYTES);

    float* wqkvT;  cudaGetSymbolAddress((void**)&wqkvT, g_wqkvT);
    float* woutT;  cudaGetSymbolAddress((void**)&woutT, g_woutT);
    float* hbuf;   cudaGetSymbolAddress((void**)&hbuf,  g_h);   // <-- R3 bug fix

    transpose_k<<<dim3(48, 16), dim3(32, 8)>>>(wqkv, wqkvT, 512, 1536);
    transpose_k<<<dim3(16, 16), dim3(32, 8)>>>(wout, woutT, 512, 512);
    gemm_mma<<<dim3(12, 256), 256>>>(x, wqkvT, bqkv, coords, gq, gk, nullptr, 0);
    window_attn<<<4096, 256, ATTN_SMEM_BYTES>>>();
    gemm_mma<<<dim3(4, 256), 256>>>(hbuf, woutT, bout, nullptr, nullptr, nullptr,
                                    outp, 1);
}

// round 5
// speedup vs baseline: 3.0667x; 1.6456x over previous
#include <cuda_runtime.h>
#include <math.h>
#include <stdint.h>

// ---------------------------------------------------------------------------
// Problem constants: N=32768 tokens, C=512, H=8, D=64; 64 windows x 512 tokens
// ---------------------------------------------------------------------------

// Scratch (static device arrays; no allocations anywhere)
__device__ float g_q[64 * 8 * 512 * 64];   // [w][h][m][d]
__device__ float g_k[64 * 8 * 512 * 64];
__device__ float g_v[64 * 8 * 512 * 64];
__device__ float g_h[32768 * 512];         // [n][h*64+d] (inverse-permuted)
__device__ float g_wqkvT[1536 * 512];      // wqkv transposed: [j][k]
__device__ float g_woutT[512 * 512];       // wout  transposed: [j][k]

// ---------------------------------------------------------------------------
// Helpers
// ---------------------------------------------------------------------------
__device__ __forceinline__ uint32_t cvt_tf32(float f) {
    uint32_t u; asm("cvt.rna.tf32.f32 %0, %1;" : "=r"(u) : "f"(f)); return u;
}

__device__ __forceinline__ void mma_tf32(float c[4], uint32_t a0, uint32_t a1,
                                         uint32_t a2, uint32_t a3,
                                         uint32_t b0, uint32_t b1) {
    asm volatile(
        "mma.sync.aligned.m16n8k8.row.col.f32.tf32.tf32.f32 "
        "{%0,%1,%2,%3}, {%4,%5,%6,%7}, {%8,%9}, {%0,%1,%2,%3};"
        : "+f"(c[0]), "+f"(c[1]), "+f"(c[2]), "+f"(c[3])
        : "r"(a0), "r"(a1), "r"(a2), "r"(a3), "r"(b0), "r"(b1));
}

// ---------------------------------------------------------------------------
// K0: 2D transpose dst[C][R] = src[R][C]
// ---------------------------------------------------------------------------
__global__ void transpose_k(const float* __restrict__ src,
                            float* __restrict__ dst, int R, int C)
{
    __shared__ float t[32][33];
    int bx = blockIdx.x << 5, by = blockIdx.y << 5;
    int x = threadIdx.x, y = threadIdx.y;   // 32 x 8
#pragma unroll
    for (int i = 0; i < 32; i += 8)
        t[y + i][x] = src[(size_t)(by + y + i) * C + bx + x];
    __syncthreads();
#pragma unroll
    for (int i = 0; i < 32; i += 8)
        dst[(size_t)(bx + y + i) * R + by + x] = t[x][y + i];
}

// ---------------------------------------------------------------------------
// tf32 mma.sync GEMM (validated in R4): C[128,128] tile, K=512.
// ---------------------------------------------------------------------------
__global__ __launch_bounds__(256, 2)
void gemm_mma(const float* __restrict__ A, const float* __restrict__ BT,
              const float* __restrict__ bias, const int* __restrict__ coords,
              const float* __restrict__ gq, const float* __restrict__ gk,
              float* __restrict__ outp, int mode)
{
    __shared__ float sA[4096];
    __shared__ float sB[4096];
    __shared__ float sBias[128];
    __shared__ float sGam[128];
    __shared__ float sRed[128][4];

    const int tid = threadIdx.x;
    const int lane = tid & 31, wid = tid >> 5;
    const int wm = wid & 1, wn = wid >> 1;
    const int gid = lane >> 2, tig = lane & 3;
    const int m0 = blockIdx.y << 7;
    const int j0 = blockIdx.x << 7;
    const int sec = j0 >> 9;

    if (tid < 128) {
        sBias[tid] = bias[j0 + tid];
        float g = 1.0f;
        if (mode == 0) {
            if (sec == 0) g = gq[(j0 & 511) + tid];
            else if (sec == 1) g = gk[(j0 & 511) + tid];
        }
        sGam[tid] = g;
    }

    float c[4][4][4];
#pragma unroll
    for (int mi = 0; mi < 4; mi++)
#pragma unroll
        for (int ni = 0; ni < 4; ni++)
#pragma unroll
            for (int q = 0; q < 4; q++) c[mi][ni][q] = 0.f;

    for (int s = 0; s < 16; s++) {
        const int kb = s << 5;
        if (s) __syncthreads();
#pragma unroll
        for (int p = 0; p < 4; p++) {
            int idx = (p << 8) + tid;
            int r = idx >> 3, cq = idx & 7;
            int tk = cq >> 1;
            float4 v = *(const float4*)&A[(size_t)(m0 + r) * 512 + kb + (cq << 2)];
            int base = ((((r >> 4) << 2) + tk) << 7) + ((r & 7) << 4)
                     + ((r >> 3) & 1) + ((cq & 1) << 1);
            sA[base + ((0 ^ tk) << 2)] = __uint_as_float(cvt_tf32(v.x));
            sA[base + ((1 ^ tk) << 2)] = __uint_as_float(cvt_tf32(v.y));
            sA[base + ((2 ^ tk) << 2)] = __uint_as_float(cvt_tf32(v.z));
            sA[base + ((3 ^ tk) << 2)] = __uint_as_float(cvt_tf32(v.w));
        }
#pragma unroll
        for (int p = 0; p < 4; p++) {
            int idx = (p << 8) + tid;
            int n = idx >> 3, kq = idx & 7;
            int tk = kq >> 1;
            float4 v = *(const float4*)&BT[(size_t)(j0 + n) * 512 + kb + (kq << 2)];
            int base = ((((n >> 4) << 2) + tk) << 7) + ((n & 7) << 4)
                     + ((kq & 1)) + (((n >> 3) & 1) << 1);
            sB[base + ((0 ^ tk) << 2)] = __uint_as_float(cvt_tf32(v.x));
            sB[base + ((1 ^ tk) << 2)] = __uint_as_float(cvt_tf32(v.y));
            sB[base + ((2 ^ tk) << 2)] = __uint_as_float(cvt_tf32(v.z));
            sB[base + ((3 ^ tk) << 2)] = __uint_as_float(cvt_tf32(v.w));
        }
        __syncthreads();
#pragma unroll
        for (int tk = 0; tk < 4; tk++) {
            const int lx = ((lane ^ tk) << 2);
            uint4 a[4];
#pragma unroll
            for (int mi = 0; mi < 4; mi++)
                a[mi] = *(const uint4*)&sA[(((((wm << 2) + mi) << 2) + tk) << 7) + lx];
            uint4 b[2];
#pragma unroll
            for (int pi = 0; pi < 2; pi++)
                b[pi] = *(const uint4*)&sB[(((((wn << 1) + pi) << 2) + tk) << 7) + lx];
#pragma unroll
            for (int mi = 0; mi < 4; mi++)
#pragma unroll
                for (int pi = 0; pi < 2; pi++) {
                    mma_tf32(c[mi][pi * 2],     a[mi].x, a[mi].y, a[mi].z, a[mi].w,
                             b[pi].x, b[pi].y);
                    mma_tf32(c[mi][pi * 2 + 1], a[mi].x, a[mi].y, a[mi].z, a[mi].w,
                             b[pi].z, b[pi].w);
                }
        }
    }

    if (mode == 1) {
#pragma unroll
        for (int mi = 0; mi < 4; mi++)
#pragma unroll
            for (int ni = 0; ni < 4; ni++) {
                int col = (wn << 5) + (ni << 3) + (tig << 1);
                int rlo = m0 + (wm << 6) + (mi << 4) + gid;
                float2 v0 = make_float2(c[mi][ni][0] + sBias[col],
                                        c[mi][ni][1] + sBias[col + 1]);
                float2 v1 = make_float2(c[mi][ni][2] + sBias[col],
                                        c[mi][ni][3] + sBias[col + 1]);
                *(float2*)&outp[(size_t)rlo * 512 + j0 + col] = v0;
                *(float2*)&outp[(size_t)(rlo + 8) * 512 + j0 + col] = v1;
            }
        return;
    }

#pragma unroll
    for (int mi = 0; mi < 4; mi++)
#pragma unroll
        for (int ni = 0; ni < 4; ni++) {
            int col = (wn << 5) + (ni << 3) + (tig << 1);
            c[mi][ni][0] += sBias[col];
            c[mi][ni][1] += sBias[col + 1];
            c[mi][ni][2] += sBias[col];
            c[mi][ni][3] += sBias[col + 1];
        }

    if (sec < 2) {
#pragma unroll
        for (int mi = 0; mi < 4; mi++)
#pragma unroll
            for (int h = 0; h < 2; h++) {
                float ss = 0.f;
#pragma unroll
                for (int ni = 0; ni < 4; ni++) {
                    float x0 = c[mi][ni][2 * h], x1 = c[mi][ni][2 * h + 1];
                    ss += x0 * x0 + x1 * x1;
                }
                ss += __shfl_xor_sync(0xffffffffu, ss, 1);
                ss += __shfl_xor_sync(0xffffffffu, ss, 2);
                if (tig == 0)
                    sRed[(wm << 6) + (mi << 4) + gid + (h << 3)][wn] = ss;
            }
        __syncthreads();
#pragma unroll
        for (int mi = 0; mi < 4; mi++)
#pragma unroll
            for (int h = 0; h < 2; h++) {
                int rl = (wm << 6) + (mi << 4) + gid + (h << 3);
                float tot = sRed[rl][wn] + sRed[rl][wn ^ 1];
                float inv = 8.0f / fmaxf(sqrtf(tot), 1e-12f);
#pragma unroll
                for (int ni = 0; ni < 4; ni++) {
                    int col = (wn << 5) + (ni << 3) + (tig << 1);
                    c[mi][ni][2 * h]     *= inv * sGam[col];
                    c[mi][ni][2 * h + 1] *= inv * sGam[col + 1];
                }
            }
    }

    float* dst = (sec == 0) ? g_q : ((sec == 1) ? g_k : g_v);
    const int head = ((j0 & 511) >> 6) + (wn >> 1);
    const int dbase = ((wn & 1) << 5) + (tig << 1);
#pragma unroll
    for (int mi = 0; mi < 4; mi++)
#pragma unroll
        for (int h = 0; h < 2; h++) {
            int token = m0 + (wm << 6) + (mi << 4) + gid + (h << 3);
            int cx = coords[4 * token + 1];
            int cy = coords[4 * token + 2];
            int cz = coords[4 * token + 3];
            int w = ((cx >> 3) << 4) + ((cy >> 3) << 2) + (cz >> 3);
            int m = ((cz & 7) << 6) + ((cy & 7) << 3) + (cx & 7);
            size_t bb = ((size_t)((w << 3) + head) * 512 + m) * 64 + dbase;
#pragma unroll
            for (int ni = 0; ni < 4; ni++)
                *(float2*)&dst[bb + (ni << 3)] =
                    make_float2(c[mi][ni][2 * h], c[mi][ni][2 * h + 1]);
        }
}

// ---------------------------------------------------------------------------
// K2: window attention via tf32 mma.sync.
// CTA = (qtile 128 rows) x (window, head).  8 warps x 16 rows.
// smem: sQ (A-frag layout, 128x64, Q pre-scaled by 0.125), per-chunk sK/sV
// (B-frag layout, 64x64).  Online softmax in registers; P permuted
// C-frag -> A-frag via shfl (no smem round-trip).
// ---------------------------------------------------------------------------
#define ATTN_SMEM_BYTES (16384 * 4)   // sQ 8192 + sK 4096 + sV 4096 floats

__global__ __launch_bounds__(256, 2)
void window_attn_mma()
{
    extern __shared__ float sm[];
    float* sQ = sm;            // 8192 floats: 64 tiles of 128 (wid*8 + kb)
    float* sK = sm + 8192;     // 4096 floats: 32 tiles (tkd*4 + tn2)
    float* sV = sm + 12288;    // 4096 floats: 32 tiles (tkey*4 + tdpair)

    const int tid = threadIdx.x;
    const int lane = tid & 31, wid = tid >> 5;
    const int gid = lane >> 2, tig = lane & 3;
    const int qt = blockIdx.x;          // 0..3
    const int wh = blockIdx.y;          // w*8 + h
    const int m0 = qt << 7;

    const float* qbase = g_q + ((size_t)wh * 512 + m0) * 64;
    const float* kbase = g_k + (size_t)wh * 512 * 64;
    const float* vbase = g_v + (size_t)wh * 512 * 64;

    // ---- stage Q once (A-frag layout, pre-scaled by 1/sqrt(D)=0.125) ----
#pragma unroll
    for (int p = 0; p < 8; p++) {
        int idx = (p << 8) + tid;       // 0..2047
        int r = idx >> 4, dq = idx & 15;
        float4 v = *(const float4*)&qbase[(size_t)r * 64 + (dq << 2)];
        int base = ((((r >> 4) << 3) + (dq >> 1)) << 7) + ((r & 7) << 4)
                 + ((r >> 3) & 1) + ((dq & 1) << 1);
        sQ[base + 0]  = __uint_as_float(cvt_tf32(v.x * 0.125f));
        sQ[base + 4]  = __uint_as_float(cvt_tf32(v.y * 0.125f));
        sQ[base + 8]  = __uint_as_float(cvt_tf32(v.z * 0.125f));
        sQ[base + 12] = __uint_as_float(cvt_tf32(v.w * 0.125f));
    }

    float cO[8][4];
#pragma unroll
    for (int f = 0; f < 8; f++)
#pragma unroll
        for (int q = 0; q < 4; q++) cO[f][q] = 0.f;
    float mr0 = -1e30f, mr1 = -1e30f, lr0 = 0.f, lr1 = 0.f;

    for (int c = 0; c < 8; c++) {
        if (c) __syncthreads();    // prior chunk's reads done
        // ---- stage K chunk (B-frag for S: n=key, k=d) ----
#pragma unroll
        for (int p = 0; p < 4; p++) {
            int idx = (p << 8) + tid;       // 0..1023
            int key = idx >> 4, dq = idx & 15;
            float4 v = *(const float4*)&kbase[(size_t)((c << 6) + key) * 64 + (dq << 2)];
            int base = ((((dq >> 1) << 2) + (key >> 4)) << 7) + ((key & 7) << 4)
                     + (dq & 1) + (((key >> 3) & 1) << 1);
            sK[base + 0]  = __uint_as_float(cvt_tf32(v.x));
            sK[base + 4]  = __uint_as_float(cvt_tf32(v.y));
            sK[base + 8]  = __uint_as_float(cvt_tf32(v.z));
            sK[base + 12] = __uint_as_float(cvt_tf32(v.w));
        }
        // ---- stage V chunk (B-frag for PV: n=d, k=key) ----
#pragma unroll
        for (int p = 0; p < 4; p++) {
            int idx = (p << 8) + tid;
            int key = idx >> 4, dq = idx & 15;
            float4 v = *(const float4*)&vbase[(size_t)((c << 6) + key) * 64 + (dq << 2)];
            int d0 = dq << 2;
            int base = ((((key >> 3) << 2) + (dq >> 2)) << 7)
                     + ((key >> 2) & 1) + (((dq >> 1) & 1) << 1)
                     + (((d0 & 7) << 2) + (key & 3)) * 4;
            // element e: d = d0+e -> lane advances by 4 floats each
            sV[base + 0]  = __uint_as_float(cvt_tf32(v.x));
            sV[base + 16] = __uint_as_float(cvt_tf32(v.y));
            sV[base + 32] = __uint_as_float(cvt_tf32(v.z));
            sV[base + 48] = __uint_as_float(cvt_tf32(v.w));
        }
        __syncthreads();

        // ---- S = Q K^T (pre-scaled) ----
        float cS[8][4];
#pragma unroll
        for (int f = 0; f < 8; f++)
#pragma unroll
            for (int q = 0; q < 4; q++) cS[f][q] = 0.f;
#pragma unroll
        for (int tkd = 0; tkd < 8; tkd++) {
            uint4 qa = *(const uint4*)&sQ[(((wid << 3) + tkd) << 7) + (lane << 2)];
#pragma unroll
            for (int tn2 = 0; tn2 < 4; tn2++) {
                uint4 kb = *(const uint4*)&sK[(((tkd << 2) + tn2) << 7) + (lane << 2)];
                mma_tf32(cS[tn2 * 2],     qa.x, qa.y, qa.z, qa.w, kb.x, kb.y);
                mma_tf32(cS[tn2 * 2 + 1], qa.x, qa.y, qa.z, qa.w, kb.z, kb.w);
            }
        }

        // ---- online softmax (rows gid, gid+8 of this warp's 16) ----
        float smax0 = -1e30f, smax1 = -1e30f;
#pragma unroll
        for (int f = 0; f < 8; f++) {
            smax0 = fmaxf(smax0, fmaxf(cS[f][0], cS[f][1]));
            smax1 = fmaxf(smax1, fmaxf(cS[f][2], cS[f][3]));
        }
        smax0 = fmaxf(smax0, __shfl_xor_sync(0xffffffffu, smax0, 1));
        smax0 = fmaxf(smax0, __shfl_xor_sync(0xffffffffu, smax0, 2));
        smax1 = fmaxf(smax1, __shfl_xor_sync(0xffffffffu, smax1, 1));
        smax1 = fmaxf(smax1, __shfl_xor_sync(0xffffffffu, smax1, 2));
        float mn0 = fmaxf(mr0, smax0), mn1 = fmaxf(mr1, smax1);
        float corr0 = __expf(mr0 - mn0), corr1 = __expf(mr1 - mn1);
        mr0 = mn0; mr1 = mn1;
        float rs0 = 0.f, rs1 = 0.f;
#pragma unroll
        for (int f = 0; f < 8; f++) {
            float p0 = __expf(cS[f][0] - mn0);
            float p1 = __expf(cS[f][1] - mn0);
            float p2 = __expf(cS[f][2] - mn1);
            float p3 = __expf(cS[f][3] - mn1);
            rs0 += p0 + p1; rs1 += p2 + p3;
            cS[f][0] = __uint_as_float(cvt_tf32(p0));
            cS[f][1] = __uint_as_float(cvt_tf32(p1));
            cS[f][2] = __uint_as_float(cvt_tf32(p2));
            cS[f][3] = __uint_as_float(cvt_tf32(p3));
        }
        rs0 += __shfl_xor_sync(0xffffffffu, rs0, 1);
        rs0 += __shfl_xor_sync(0xffffffffu, rs0, 2);
        rs1 += __shfl_xor_sync(0xffffffffu, rs1, 1);
        rs1 += __shfl_xor_sync(0xffffffffu, rs1, 2);
        lr0 = lr0 * corr0 + rs0;
        lr1 = lr1 * corr1 + rs1;
#pragma unroll
        for (int f = 0; f < 8; f++) {
            cO[f][0] *= corr0; cO[f][1] *= corr0;
            cO[f][2] *= corr1; cO[f][3] *= corr1;
        }

        // ---- O += P V : permute P C-frag -> A-frag via shfl, then mma ----
        const int src  = (lane & 28) | (tig >> 1);
        const int src2 = src + 2;
        const bool odd = tig & 1;
#pragma unroll
        for (int kb = 0; kb < 8; kb++) {
            float v0 = __shfl_sync(0xffffffffu, cS[kb][0], src);
            float v1 = __shfl_sync(0xffffffffu, cS[kb][1], src);
            float v2 = __shfl_sync(0xffffffffu, cS[kb][2], src);
            float v3 = __shfl_sync(0xffffffffu, cS[kb][3], src);
            float w0 = __shfl_sync(0xffffffffu, cS[kb][0], src2);
            float w1 = __shfl_sync(0xffffffffu, cS[kb][1], src2);
            float w2 = __shfl_sync(0xffffffffu, cS[kb][2], src2);
            float w3 = __shfl_sync(0xffffffffu, cS[kb][3], src2);
            uint32_t pa0 = __float_as_uint(odd ? v1 : v0);
            uint32_t pa1 = __float_as_uint(odd ? v3 : v2);
            uint32_t pa2 = __float_as_uint(odd ? w1 : w0);
            uint32_t pa3 = __float_as_uint(odd ? w3 : w2);
#pragma unroll
            for (int tn = 0; tn < 4; tn++) {
                uint4 vb = *(const uint4*)&sV[(((kb << 2) + tn) << 7) + (lane << 2)];
                mma_tf32(cO[tn * 2],     pa0, pa1, pa2, pa3, vb.x, vb.y);
                mma_tf32(cO[tn * 2 + 1], pa0, pa1, pa2, pa3, vb.z, vb.w);
            }
        }
    }

    // ---- epilogue: 1/l and inverse-permutation scatter ----
    const int w = wh >> 3, h = wh & 7;
    const int wx = w >> 4, wy = (w >> 2) & 3, wz = w & 3;
    const float invl0 = 1.0f / lr0, invl1 = 1.0f / lr1;
#pragma unroll
    for (int rr = 0; rr < 2; rr++) {
        int m = m0 + (wid << 4) + gid + (rr << 3);
        int mz = m >> 6, my = (m >> 3) & 7, mx = m & 7;
        int n = (wz * 8 + mz) * 1024 + (wy * 8 + my) * 32 + (wx * 8 + mx);
        float inv = rr ? invl1 : invl0;
        float* dsth = g_h + (size_t)n * 512 + h * 64 + (tig << 1);
#pragma unroll
        for (int f = 0; f < 8; f++)
            *(float2*)&dsth[f << 3] =
                make_float2(cO[f][2 * rr] * inv, cO[f][2 * rr + 1] * inv);
    }
}

// ---------------------------------------------------------------------------
// kernel_launch
// inputs: x_feats, coords, w_qkv, b_qkv, gamma_q, gamma_k, w_out, b_out
// ---------------------------------------------------------------------------
extern "C" void kernel_launch(void* const* d_in, const int* in_sizes, int n_in,
                              void* d_out, int out_size)
{
    (void)in_sizes; (void)n_in; (void)out_size;
    const float* x      = (const float*)d_in[0];
    const int*   coords = (const int*)  d_in[1];
    const float* wqkv   = (const float*)d_in[2];
    const float* bqkv   = (const float*)d_in[3];
    const float* gq     = (const float*)d_in[4];
    const float* gk     = (const float*)d_in[5];
    const float* wout   = (const float*)d_in[6];
    const float* bout   = (const float*)d_in[7];
    float* outp = (float*)d_out;

    cudaFuncSetAttribute(window_attn_mma,
                         cudaFuncAttributeMaxDynamicSharedMemorySize,
                         ATTN_SMEM_BYTES);

    float* wqkvT;  cudaGetSymbolAddress((void**)&wqkvT, g_wqkvT);
    float* woutT;  cudaGetSymbolAddress((void**)&woutT, g_woutT);
    float* hbuf;   cudaGetSymbolAddress((void**)&hbuf,  g_h);

    transpose_k<<<dim3(48, 16), dim3(32, 8)>>>(wqkv, wqkvT, 512, 1536);
    transpose_k<<<dim3(16, 16), dim3(32, 8)>>>(wout, woutT, 512, 512);
    gemm_mma<<<dim3(12, 256), 256>>>(x, wqkvT, bqkv, coords, gq, gk, nullptr, 0);
    window_attn_mma<<<dim3(4, 512), 256, ATTN_SMEM_BYTES>>>();
    gemm_mma<<<dim3(4, 256), 256>>>(hbuf, woutT, bout, nullptr, nullptr, nullptr,
                                    outp, 1);
}

// round 6
// speedup vs baseline: 3.2003x; 1.0436x over previous
#include <cuda_runtime.h>
#include <math.h>
#include <stdint.h>

// ---------------------------------------------------------------------------
// Problem constants: N=32768 tokens, C=512, H=8, D=64; 64 windows x 512 tokens
// ---------------------------------------------------------------------------

// Scratch (static device arrays; no allocations anywhere)
__device__ float g_q[64 * 8 * 512 * 64];   // [w][h][m][d]
__device__ float g_k[64 * 8 * 512 * 64];
__device__ float g_v[64 * 8 * 512 * 64];
__device__ float g_h[32768 * 512];         // [n][h*64+d] (inverse-permuted)
__device__ float g_wqkvT[1536 * 512];      // wqkv transposed: [j][k]
__device__ float g_woutT[512 * 512];       // wout  transposed: [j][k]

// ---------------------------------------------------------------------------
// Helpers
// ---------------------------------------------------------------------------
__device__ __forceinline__ uint32_t cvt_tf32(float f) {
    uint32_t u; asm("cvt.rna.tf32.f32 %0, %1;" : "=r"(u) : "f"(f)); return u;
}

__device__ __forceinline__ void mma_tf32(float c[4], uint32_t a0, uint32_t a1,
                                         uint32_t a2, uint32_t a3,
                                         uint32_t b0, uint32_t b1) {
    asm volatile(
        "mma.sync.aligned.m16n8k8.row.col.f32.tf32.tf32.f32 "
        "{%0,%1,%2,%3}, {%4,%5,%6,%7}, {%8,%9}, {%0,%1,%2,%3};"
        : "+f"(c[0]), "+f"(c[1]), "+f"(c[2]), "+f"(c[3])
        : "r"(a0), "r"(a1), "r"(a2), "r"(a3), "r"(b0), "r"(b1));
}

// ---------------------------------------------------------------------------
// K0: 2D transpose dst[C][R] = src[R][C]
// ---------------------------------------------------------------------------
__global__ void transpose_k(const float* __restrict__ src,
                            float* __restrict__ dst, int R, int C)
{
    __shared__ float t[32][33];
    int bx = blockIdx.x << 5, by = blockIdx.y << 5;
    int x = threadIdx.x, y = threadIdx.y;   // 32 x 8
#pragma unroll
    for (int i = 0; i < 32; i += 8)
        t[y + i][x] = src[(size_t)(by + y + i) * C + bx + x];
    __syncthreads();
#pragma unroll
    for (int i = 0; i < 32; i += 8)
        dst[(size_t)(bx + y + i) * R + by + x] = t[x][y + i];
}

// ---------------------------------------------------------------------------
// tf32 mma.sync GEMM (validated in R4): C[128,128] tile, K=512.
// ---------------------------------------------------------------------------
__global__ __launch_bounds__(256, 2)
void gemm_mma(const float* __restrict__ A, const float* __restrict__ BT,
              const float* __restrict__ bias, const int* __restrict__ coords,
              const float* __restrict__ gq, const float* __restrict__ gk,
              float* __restrict__ outp, int mode)
{
    __shared__ float sA[4096];
    __shared__ float sB[4096];
    __shared__ float sBias[128];
    __shared__ float sGam[128];
    __shared__ float sRed[128][4];

    const int tid = threadIdx.x;
    const int lane = tid & 31, wid = tid >> 5;
    const int wm = wid & 1, wn = wid >> 1;
    const int gid = lane >> 2, tig = lane & 3;
    const int m0 = blockIdx.y << 7;
    const int j0 = blockIdx.x << 7;
    const int sec = j0 >> 9;

    if (tid < 128) {
        sBias[tid] = bias[j0 + tid];
        float g = 1.0f;
        if (mode == 0) {
            if (sec == 0) g = gq[(j0 & 511) + tid];
            else if (sec == 1) g = gk[(j0 & 511) + tid];
        }
        sGam[tid] = g;
    }

    float c[4][4][4];
#pragma unroll
    for (int mi = 0; mi < 4; mi++)
#pragma unroll
        for (int ni = 0; ni < 4; ni++)
#pragma unroll
            for (int q = 0; q < 4; q++) c[mi][ni][q] = 0.f;

    for (int s = 0; s < 16; s++) {
        const int kb = s << 5;
        if (s) __syncthreads();
#pragma unroll
        for (int p = 0; p < 4; p++) {
            int idx = (p << 8) + tid;
            int r = idx >> 3, cq = idx & 7;
            int tk = cq >> 1;
            float4 v = *(const float4*)&A[(size_t)(m0 + r) * 512 + kb + (cq << 2)];
            int base = ((((r >> 4) << 2) + tk) << 7) + ((r & 7) << 4)
                     + ((r >> 3) & 1) + ((cq & 1) << 1);
            sA[base + ((0 ^ tk) << 2)] = __uint_as_float(cvt_tf32(v.x));
            sA[base + ((1 ^ tk) << 2)] = __uint_as_float(cvt_tf32(v.y));
            sA[base + ((2 ^ tk) << 2)] = __uint_as_float(cvt_tf32(v.z));
            sA[base + ((3 ^ tk) << 2)] = __uint_as_float(cvt_tf32(v.w));
        }
#pragma unroll
        for (int p = 0; p < 4; p++) {
            int idx = (p << 8) + tid;
            int n = idx >> 3, kq = idx & 7;
            int tk = kq >> 1;
            float4 v = *(const float4*)&BT[(size_t)(j0 + n) * 512 + kb + (kq << 2)];
            int base = ((((n >> 4) << 2) + tk) << 7) + ((n & 7) << 4)
                     + ((kq & 1)) + (((n >> 3) & 1) << 1);
            sB[base + ((0 ^ tk) << 2)] = __uint_as_float(cvt_tf32(v.x));
            sB[base + ((1 ^ tk) << 2)] = __uint_as_float(cvt_tf32(v.y));
            sB[base + ((2 ^ tk) << 2)] = __uint_as_float(cvt_tf32(v.z));
            sB[base + ((3 ^ tk) << 2)] = __uint_as_float(cvt_tf32(v.w));
        }
        __syncthreads();
#pragma unroll
        for (int tk = 0; tk < 4; tk++) {
            const int lx = ((lane ^ tk) << 2);
            uint4 a[4];
#pragma unroll
            for (int mi = 0; mi < 4; mi++)
                a[mi] = *(const uint4*)&sA[(((((wm << 2) + mi) << 2) + tk) << 7) + lx];
            uint4 b[2];
#pragma unroll
            for (int pi = 0; pi < 2; pi++)
                b[pi] = *(const uint4*)&sB[(((((wn << 1) + pi) << 2) + tk) << 7) + lx];
#pragma unroll
            for (int mi = 0; mi < 4; mi++)
#pragma unroll
                for (int pi = 0; pi < 2; pi++) {
                    mma_tf32(c[mi][pi * 2],     a[mi].x, a[mi].y, a[mi].z, a[mi].w,
                             b[pi].x, b[pi].y);
                    mma_tf32(c[mi][pi * 2 + 1], a[mi].x, a[mi].y, a[mi].z, a[mi].w,
                             b[pi].z, b[pi].w);
                }
        }
    }

    if (mode == 1) {
#pragma unroll
        for (int mi = 0; mi < 4; mi++)
#pragma unroll
            for (int ni = 0; ni < 4; ni++) {
                int col = (wn << 5) + (ni << 3) + (tig << 1);
                int rlo = m0 + (wm << 6) + (mi << 4) + gid;
                float2 v0 = make_float2(c[mi][ni][0] + sBias[col],
                                        c[mi][ni][1] + sBias[col + 1]);
                float2 v1 = make_float2(c[mi][ni][2] + sBias[col],
                                        c[mi][ni][3] + sBias[col + 1]);
                *(float2*)&outp[(size_t)rlo * 512 + j0 + col] = v0;
                *(float2*)&outp[(size_t)(rlo + 8) * 512 + j0 + col] = v1;
            }
        return;
    }

#pragma unroll
    for (int mi = 0; mi < 4; mi++)
#pragma unroll
        for (int ni = 0; ni < 4; ni++) {
            int col = (wn << 5) + (ni << 3) + (tig << 1);
            c[mi][ni][0] += sBias[col];
            c[mi][ni][1] += sBias[col + 1];
            c[mi][ni][2] += sBias[col];
            c[mi][ni][3] += sBias[col + 1];
        }

    if (sec < 2) {
#pragma unroll
        for (int mi = 0; mi < 4; mi++)
#pragma unroll
            for (int h = 0; h < 2; h++) {
                float ss = 0.f;
#pragma unroll
                for (int ni = 0; ni < 4; ni++) {
                    float x0 = c[mi][ni][2 * h], x1 = c[mi][ni][2 * h + 1];
                    ss += x0 * x0 + x1 * x1;
                }
                ss += __shfl_xor_sync(0xffffffffu, ss, 1);
                ss += __shfl_xor_sync(0xffffffffu, ss, 2);
                if (tig == 0)
                    sRed[(wm << 6) + (mi << 4) + gid + (h << 3)][wn] = ss;
            }
        __syncthreads();
#pragma unroll
        for (int mi = 0; mi < 4; mi++)
#pragma unroll
            for (int h = 0; h < 2; h++) {
                int rl = (wm << 6) + (mi << 4) + gid + (h << 3);
                float tot = sRed[rl][wn] + sRed[rl][wn ^ 1];
                float inv = 8.0f / fmaxf(sqrtf(tot), 1e-12f);
#pragma unroll
                for (int ni = 0; ni < 4; ni++) {
                    int col = (wn << 5) + (ni << 3) + (tig << 1);
                    c[mi][ni][2 * h]     *= inv * sGam[col];
                    c[mi][ni][2 * h + 1] *= inv * sGam[col + 1];
                }
            }
    }

    float* dst = (sec == 0) ? g_q : ((sec == 1) ? g_k : g_v);
    const int head = ((j0 & 511) >> 6) + (wn >> 1);
    const int dbase = ((wn & 1) << 5) + (tig << 1);
#pragma unroll
    for (int mi = 0; mi < 4; mi++)
#pragma unroll
        for (int h = 0; h < 2; h++) {
            int token = m0 + (wm << 6) + (mi << 4) + gid + (h << 3);
            int cx = coords[4 * token + 1];
            int cy = coords[4 * token + 2];
            int cz = coords[4 * token + 3];
            int w = ((cx >> 3) << 4) + ((cy >> 3) << 2) + (cz >> 3);
            int m = ((cz & 7) << 6) + ((cy & 7) << 3) + (cx & 7);
            size_t bb = ((size_t)((w << 3) + head) * 512 + m) * 64 + dbase;
#pragma unroll
            for (int ni = 0; ni < 4; ni++)
                *(float2*)&dst[bb + (ni << 3)] =
                    make_float2(c[mi][ni][2 * h], c[mi][ni][2 * h + 1]);
        }
}

// ---------------------------------------------------------------------------
// K2: window attention via tf32 mma.sync — 32-row warp tiles.
// CTA = (qtile 256 rows) x (window, head).  8 warps x 32 rows (2 m16 tiles).
// K/V fragment loads amortized over both m-tiles: 80 LDS.128 per 256 MMAs
// per warp per chunk (was 72/128).  Same frag algebra / shfl P-permute as R5.
// ---------------------------------------------------------------------------
#define ATTN_SMEM_BYTES ((16384 + 4096 + 4096) * 4)   // sQ + sK + sV floats

__global__ __launch_bounds__(256, 1)
void window_attn_mma()
{
    extern __shared__ float sm[];
    float* sQ = sm;             // 16384 floats: 128 frag tiles (mt*8 + tkd)
    float* sK = sm + 16384;     // 4096 floats: 32 tiles (tkd*4 + tn2)
    float* sV = sm + 20480;     // 4096 floats: 32 tiles (tkey*4 + tdpair)

    const int tid = threadIdx.x;
    const int lane = tid & 31, wid = tid >> 5;
    const int gid = lane >> 2, tig = lane & 3;
    const int qt = blockIdx.x;          // 0..1
    const int wh = blockIdx.y;          // w*8 + h
    const int m0 = qt << 8;             // 256 rows per CTA

    const float* qbase = g_q + ((size_t)wh * 512 + m0) * 64;
    const float* kbase = g_k + (size_t)wh * 512 * 64;
    const float* vbase = g_v + (size_t)wh * 512 * 64;

    // ---- stage Q once (A-frag layout, pre-scaled by 1/sqrt(D)=0.125) ----
#pragma unroll
    for (int p = 0; p < 16; p++) {
        int idx = (p << 8) + tid;       // 0..4095
        int r = idx >> 4, dq = idx & 15;
        float4 v = *(const float4*)&qbase[(size_t)r * 64 + (dq << 2)];
        int base = ((((r >> 4) << 3) + (dq >> 1)) << 7) + ((r & 7) << 4)
                 + ((r >> 3) & 1) + ((dq & 1) << 1);
        sQ[base + 0]  = __uint_as_float(cvt_tf32(v.x * 0.125f));
        sQ[base + 4]  = __uint_as_float(cvt_tf32(v.y * 0.125f));
        sQ[base + 8]  = __uint_as_float(cvt_tf32(v.z * 0.125f));
        sQ[base + 12] = __uint_as_float(cvt_tf32(v.w * 0.125f));
    }

    float cO[2][8][4];
#pragma unroll
    for (int mi = 0; mi < 2; mi++)
#pragma unroll
        for (int f = 0; f < 8; f++)
#pragma unroll
            for (int q = 0; q < 4; q++) cO[mi][f][q] = 0.f;
    float mr[2][2], lr[2][2];
#pragma unroll
    for (int mi = 0; mi < 2; mi++) {
        mr[mi][0] = -1e30f; mr[mi][1] = -1e30f;
        lr[mi][0] = 0.f;    lr[mi][1] = 0.f;
    }

    for (int c = 0; c < 8; c++) {
        if (c) __syncthreads();    // prior chunk's K/V reads done
        // ---- stage K chunk (B-frag for S: n=key, k=d) ----
#pragma unroll
        for (int p = 0; p < 4; p++) {
            int idx = (p << 8) + tid;       // 0..1023
            int key = idx >> 4, dq = idx & 15;
            float4 v = *(const float4*)&kbase[(size_t)((c << 6) + key) * 64 + (dq << 2)];
            int base = ((((dq >> 1) << 2) + (key >> 4)) << 7) + ((key & 7) << 4)
                     + (dq & 1) + (((key >> 3) & 1) << 1);
            sK[base + 0]  = __uint_as_float(cvt_tf32(v.x));
            sK[base + 4]  = __uint_as_float(cvt_tf32(v.y));
            sK[base + 8]  = __uint_as_float(cvt_tf32(v.z));
            sK[base + 12] = __uint_as_float(cvt_tf32(v.w));
        }
        // ---- stage V chunk (B-frag for PV: n=d, k=key) ----
#pragma unroll
        for (int p = 0; p < 4; p++) {
            int idx = (p << 8) + tid;
            int key = idx >> 4, dq = idx & 15;
            float4 v = *(const float4*)&vbase[(size_t)((c << 6) + key) * 64 + (dq << 2)];
            int d0 = dq << 2;
            int base = ((((key >> 3) << 2) + (dq >> 2)) << 7)
                     + ((key >> 2) & 1) + (((dq >> 1) & 1) << 1)
                     + (((d0 & 7) << 2) + (key & 3)) * 4;
            sV[base + 0]  = __uint_as_float(cvt_tf32(v.x));
            sV[base + 16] = __uint_as_float(cvt_tf32(v.y));
            sV[base + 32] = __uint_as_float(cvt_tf32(v.z));
            sV[base + 48] = __uint_as_float(cvt_tf32(v.w));
        }
        __syncthreads();

        // ---- S = Q K^T (pre-scaled): 2 m-tiles x 8 n-tiles ----
        float cS[2][8][4];
#pragma unroll
        for (int mi = 0; mi < 2; mi++)
#pragma unroll
            for (int f = 0; f < 8; f++)
#pragma unroll
                for (int q = 0; q < 4; q++) cS[mi][f][q] = 0.f;
#pragma unroll
        for (int tkd = 0; tkd < 8; tkd++) {
            uint4 qa[2];
#pragma unroll
            for (int mi = 0; mi < 2; mi++)
                qa[mi] = *(const uint4*)&sQ[(((((wid << 1) + mi) << 3) + tkd) << 7)
                                            + (lane << 2)];
#pragma unroll
            for (int tn2 = 0; tn2 < 4; tn2++) {
                uint4 kb = *(const uint4*)&sK[(((tkd << 2) + tn2) << 7) + (lane << 2)];
#pragma unroll
                for (int mi = 0; mi < 2; mi++) {
                    mma_tf32(cS[mi][tn2 * 2],     qa[mi].x, qa[mi].y, qa[mi].z,
                             qa[mi].w, kb.x, kb.y);
                    mma_tf32(cS[mi][tn2 * 2 + 1], qa[mi].x, qa[mi].y, qa[mi].z,
                             qa[mi].w, kb.z, kb.w);
                }
            }
        }

        // ---- online softmax per m-tile (rows gid, gid+8) ----
#pragma unroll
        for (int mi = 0; mi < 2; mi++) {
            float smax0 = -1e30f, smax1 = -1e30f;
#pragma unroll
            for (int f = 0; f < 8; f++) {
                smax0 = fmaxf(smax0, fmaxf(cS[mi][f][0], cS[mi][f][1]));
                smax1 = fmaxf(smax1, fmaxf(cS[mi][f][2], cS[mi][f][3]));
            }
            smax0 = fmaxf(smax0, __shfl_xor_sync(0xffffffffu, smax0, 1));
            smax0 = fmaxf(smax0, __shfl_xor_sync(0xffffffffu, smax0, 2));
            smax1 = fmaxf(smax1, __shfl_xor_sync(0xffffffffu, smax1, 1));
            smax1 = fmaxf(smax1, __shfl_xor_sync(0xffffffffu, smax1, 2));
            float mn0 = fmaxf(mr[mi][0], smax0), mn1 = fmaxf(mr[mi][1], smax1);
            float corr0 = __expf(mr[mi][0] - mn0), corr1 = __expf(mr[mi][1] - mn1);
            mr[mi][0] = mn0; mr[mi][1] = mn1;
            float rs0 = 0.f, rs1 = 0.f;
#pragma unroll
            for (int f = 0; f < 8; f++) {
                float p0 = __expf(cS[mi][f][0] - mn0);
                float p1 = __expf(cS[mi][f][1] - mn0);
                float p2 = __expf(cS[mi][f][2] - mn1);
                float p3 = __expf(cS[mi][f][3] - mn1);
                rs0 += p0 + p1; rs1 += p2 + p3;
                cS[mi][f][0] = __uint_as_float(cvt_tf32(p0));
                cS[mi][f][1] = __uint_as_float(cvt_tf32(p1));
                cS[mi][f][2] = __uint_as_float(cvt_tf32(p2));
                cS[mi][f][3] = __uint_as_float(cvt_tf32(p3));
            }
            rs0 += __shfl_xor_sync(0xffffffffu, rs0, 1);
            rs0 += __shfl_xor_sync(0xffffffffu, rs0, 2);
            rs1 += __shfl_xor_sync(0xffffffffu, rs1, 1);
            rs1 += __shfl_xor_sync(0xffffffffu, rs1, 2);
            lr[mi][0] = lr[mi][0] * corr0 + rs0;
            lr[mi][1] = lr[mi][1] * corr1 + rs1;
#pragma unroll
            for (int f = 0; f < 8; f++) {
                cO[mi][f][0] *= corr0; cO[mi][f][1] *= corr0;
                cO[mi][f][2] *= corr1; cO[mi][f][3] *= corr1;
            }
        }

        // ---- O += P V : shfl P C-frag -> A-frag; V frags reused by both mi ----
        const int src  = (lane & 28) | (tig >> 1);
        const int src2 = src + 2;
        const bool odd = tig & 1;
#pragma unroll
        for (int kb = 0; kb < 8; kb++) {
            uint32_t pa[2][4];
#pragma unroll
            for (int mi = 0; mi < 2; mi++) {
                float v0 = __shfl_sync(0xffffffffu, cS[mi][kb][0], src);
                float v1 = __shfl_sync(0xffffffffu, cS[mi][kb][1], src);
                float v2 = __shfl_sync(0xffffffffu, cS[mi][kb][2], src);
                float v3 = __shfl_sync(0xffffffffu, cS[mi][kb][3], src);
                float w0 = __shfl_sync(0xffffffffu, cS[mi][kb][0], src2);
                float w1 = __shfl_sync(0xffffffffu, cS[mi][kb][1], src2);
                float w2 = __shfl_sync(0xffffffffu, cS[mi][kb][2], src2);
                float w3 = __shfl_sync(0xffffffffu, cS[mi][kb][3], src2);
                pa[mi][0] = __float_as_uint(odd ? v1 : v0);
                pa[mi][1] = __float_as_uint(odd ? v3 : v2);
                pa[mi][2] = __float_as_uint(odd ? w1 : w0);
                pa[mi][3] = __float_as_uint(odd ? w3 : w2);
            }
#pragma unroll
            for (int tn = 0; tn < 4; tn++) {
                uint4 vb = *(const uint4*)&sV[(((kb << 2) + tn) << 7) + (lane << 2)];
#pragma unroll
                for (int mi = 0; mi < 2; mi++) {
                    mma_tf32(cO[mi][tn * 2],     pa[mi][0], pa[mi][1], pa[mi][2],
                             pa[mi][3], vb.x, vb.y);
                    mma_tf32(cO[mi][tn * 2 + 1], pa[mi][0], pa[mi][1], pa[mi][2],
                             pa[mi][3], vb.z, vb.w);
                }
            }
        }
    }

    // ---- epilogue: 1/l and inverse-permutation scatter ----
    const int w = wh >> 3, h = wh & 7;
    const int wx = w >> 4, wy = (w >> 2) & 3, wz = w & 3;
#pragma unroll
    for (int mi = 0; mi < 2; mi++)
#pragma unroll
        for (int rr = 0; rr < 2; rr++) {
            int m = m0 + (wid << 5) + (mi << 4) + gid + (rr << 3);
            int mz = m >> 6, my = (m >> 3) & 7, mx = m & 7;
            int n = (wz * 8 + mz) * 1024 + (wy * 8 + my) * 32 + (wx * 8 + mx);
            float inv = 1.0f / lr[mi][rr];
            float* dsth = g_h + (size_t)n * 512 + h * 64 + (tig << 1);
#pragma unroll
            for (int f = 0; f < 8; f++)
                *(float2*)&dsth[f << 3] =
                    make_float2(cO[mi][f][2 * rr] * inv,
                                cO[mi][f][2 * rr + 1] * inv);
        }
}

// ---------------------------------------------------------------------------
// kernel_launch
// inputs: x_feats, coords, w_qkv, b_qkv, gamma_q, gamma_k, w_out, b_out
// ---------------------------------------------------------------------------
extern "C" void kernel_launch(void* const* d_in, const int* in_sizes, int n_in,
                              void* d_out, int out_size)
{
    (void)in_sizes; (void)n_in; (void)out_size;
    const float* x      = (const float*)d_in[0];
    const int*   coords = (const int*)  d_in[1];
    const float* wqkv   = (const float*)d_in[2];
    const float* bqkv   = (const float*)d_in[3];
    const float* gq     = (const float*)d_in[4];
    const float* gk     = (const float*)d_in[5];
    const float* wout   = (const float*)d_in[6];
    const float* bout   = (const float*)d_in[7];
    float* outp = (float*)d_out;

    cudaFuncSetAttribute(window_attn_mma,
                         cudaFuncAttributeMaxDynamicSharedMemorySize,
                         ATTN_SMEM_BYTES);

    float* wqkvT;  cudaGetSymbolAddress((void**)&wqkvT, g_wqkvT);
    float* woutT;  cudaGetSymbolAddress((void**)&woutT, g_woutT);
    float* hbuf;   cudaGetSymbolAddress((void**)&hbuf,  g_h);

    transpose_k<<<dim3(48, 16), dim3(32, 8)>>>(wqkv, wqkvT, 512, 1536);
    transpose_k<<<dim3(16, 16), dim3(32, 8)>>>(wout, woutT, 512, 512);
    gemm_mma<<<dim3(12, 256), 256>>>(x, wqkvT, bqkv, coords, gq, gk, nullptr, 0);
    window_attn_mma<<<dim3(2, 512), 256, ATTN_SMEM_BYTES>>>();
    gemm_mma<<<dim3(4, 256), 256>>>(hbuf, woutT, bout, nullptr, nullptr, nullptr,
                                    outp, 1);
}